// round 9
// baseline (speedup 1.0000x reference)
#include <cuda_runtime.h>
#include <cstdint>

// Router_63900523430579 (GB300/sm_103): scores = x[32768,2048] @ W[64,2048]^T
// Single fused persistent kernel: tf32 mma.sync GEMM + top-2 epilogue,
// grid-wide arrival barrier, then fp64 fixup of ambiguous tokens + aux loss.
// out f32: [0,65536) top2 idx ; [65536,131072) top2 weights ; [131072] aux loss

#define KDIM   2048
#define NTOK   32768
#define NEXP   64
#define MTILE  128
#define NCTA   (NTOK / MTILE)          // 256
#define CK     32
#define NCHUNK (KDIM / CK)             // 64
#define RW     40
#define STAGEF ((MTILE + NEXP) * RW)   // 7680 floats = 30720 B / stage
#define NSTAGE 3
#define SMEM_REQ (NSTAGE * STAGEF * 4) // 92160 B  (2 CTAs/SM)
#define DELTA1 3.0e-3f

__device__ int      g_done, g_done2, g_cnt1, g_cnt2;     // zero-init; reset at end
__device__ float    g_part[NCTA * NEXP];
__device__ int      g_list1[NTOK], g_list2[NTOK];
__device__ unsigned g_cand[NTOK];

__device__ __forceinline__ void mma8(float* d, uint32_t a0, uint32_t a1,
                                     uint32_t a2, uint32_t a3,
                                     uint32_t b0, uint32_t b1) {
    asm volatile("mma.sync.aligned.m16n8k8.row.col.f32.tf32.tf32.f32 "
                 "{%0,%1,%2,%3},{%4,%5,%6,%7},{%8,%9},{%0,%1,%2,%3};"
                 : "+f"(d[0]), "+f"(d[1]), "+f"(d[2]), "+f"(d[3])
                 : "r"(a0), "r"(a1), "r"(a2), "r"(a3), "r"(b0), "r"(b1));
}
__device__ __forceinline__ void cp16(uint32_t s, const void* g) {
    asm volatile("cp.async.cg.shared.global [%0], [%1], 16;\n" :: "r"(s), "l"(g));
}
#define CP_COMMIT() asm volatile("cp.async.commit_group;\n")
#define CP_WAIT(n)  asm volatile("cp.async.wait_group %0;\n" :: "n"(n))

__global__ void __launch_bounds__(256, 2)
fused_kernel(const float* __restrict__ x, const float* __restrict__ W,
             float* __restrict__ out) {
    extern __shared__ float sm[];
    const uint32_t smb = (uint32_t)__cvta_generic_to_shared(sm);
    const int tid = threadIdx.x;
    const int wid = tid >> 5, lane = tid & 31;
    const int lq = lane & 3, lr = lane >> 2;

    // ================= PHASE A: GEMM tile =================
    const float* xg = x + (size_t)blockIdx.x * MTILE * KDIM;

    auto issue_chunk = [&](int c) {
        uint32_t st = smb + (uint32_t)((c % NSTAGE) * STAGEF) * 4u;
        #pragma unroll
        for (int v = 0; v < 4; v++) {                 // x: 128 rows x 8 float4
            int fi = tid + 256 * v;
            int r = fi >> 3, j = fi & 7;
            cp16(st + (uint32_t)(r * RW + j * 4) * 4u,
                 xg + (size_t)r * KDIM + c * CK + j * 4);
        }
        #pragma unroll
        for (int v = 0; v < 2; v++) {                 // W: 64 rows x 8 float4
            int fi = tid + 256 * v;
            int e = fi >> 3, j = fi & 7;
            cp16(st + (uint32_t)(MTILE * RW + e * RW + j * 4) * 4u,
                 W + (size_t)e * KDIM + c * CK + j * 4);
        }
        CP_COMMIT();
    };

    float acc[8][4];
    #pragma unroll
    for (int j = 0; j < 8; j++)
        #pragma unroll
        for (int v = 0; v < 4; v++) acc[j][v] = 0.0f;

    issue_chunk(0); issue_chunk(1);

    for (int c = 0; c < NCHUNK; c++) {
        if (c < NCHUNK - 2) CP_WAIT(1);
        else                CP_WAIT(0);
        __syncthreads();
        if (c + 2 < NCHUNK) issue_chunk(c + 2);

        const float* xb = sm + (c % NSTAGE) * STAGEF;
        const float* wb = xb + MTILE * RW;
        #pragma unroll
        for (int s = 0; s < 4; s++) {
            const float* xr = xb + (wid * 16 + lr) * RW + s * 8 + lq;
            uint32_t a0 = __float_as_uint(xr[0]);
            uint32_t a1 = __float_as_uint(xr[8 * RW]);
            uint32_t a2 = __float_as_uint(xr[4]);
            uint32_t a3 = __float_as_uint(xr[8 * RW + 4]);
            #pragma unroll
            for (int j = 0; j < 8; j++) {
                const float* wr = wb + (j * 8 + lr) * RW + s * 8 + lq;
                mma8(acc[j], a0, a1, a2, a3,
                     __float_as_uint(wr[0]), __float_as_uint(wr[4]));
            }
        }
    }
    __syncthreads();

    // ---- epilogue overlay: sc[128][65], mm[128], iz[128], red[4][64] ----
    float* sc = sm;
    float* mm = sc + 128 * 65;
    float* iz = mm + 128;
    float* red = iz + 128;

    {
        int r0 = wid * 16 + lr;
        #pragma unroll
        for (int j = 0; j < 8; j++) {
            sc[r0 * 65 + j * 8 + 2 * lq]           = acc[j][0];
            sc[r0 * 65 + j * 8 + 2 * lq + 1]       = acc[j][1];
            sc[(r0 + 8) * 65 + j * 8 + 2 * lq]     = acc[j][2];
            sc[(r0 + 8) * 65 + j * 8 + 2 * lq + 1] = acc[j][3];
        }
    }
    __syncthreads();

    if (tid < 128) {    // one token per thread: top-4, softmax, ambiguity routing
        const int t = tid;
        const float* row = sc + t * 65;
        float m[4] = {-3e38f, -3e38f, -3e38f, -3e38f};
        int   id[4] = {0, 0, 0, 0};
        #pragma unroll 8
        for (int e = 0; e < 64; e++) {
            float v = row[e];
            if (v > m[0])      { m[3]=m[2]; id[3]=id[2]; m[2]=m[1]; id[2]=id[1];
                                 m[1]=m[0]; id[1]=id[0]; m[0]=v; id[0]=e; }
            else if (v > m[1]) { m[3]=m[2]; id[3]=id[2]; m[2]=m[1]; id[2]=id[1];
                                 m[1]=v; id[1]=e; }
            else if (v > m[2]) { m[3]=m[2]; id[3]=id[2]; m[2]=v; id[2]=e; }
            else if (v > m[3]) { m[3]=v; id[3]=e; }
        }
        float Z = 0.0f;
        #pragma unroll 8
        for (int e = 0; e < 64; e++) Z += __expf(row[e] - m[0]);
        mm[t] = m[0];
        iz[t] = 1.0f / Z;

        float e2 = __expf(m[1] - m[0]);
        float w1 = 1.0f / (1.0f + e2);
        size_t T = (size_t)blockIdx.x * MTILE + t;
        out[2 * T]     = (float)id[0];
        out[2 * T + 1] = (float)id[1];
        out[2 * (size_t)NTOK + 2 * T]     = w1;
        out[2 * (size_t)NTOK + 2 * T + 1] = e2 * w1;

        if ((m[0] - m[1]) < DELTA1 || (m[1] - m[2]) < DELTA1) {
            if ((m[1] - m[3]) < DELTA1) {
                int q = atomicAdd(&g_cnt2, 1);
                g_list2[q] = (int)T;
            } else {
                int q = atomicAdd(&g_cnt1, 1);
                g_list1[q] = (int)T;
                g_cand[q] = (unsigned)id[0] | ((unsigned)id[1] << 8) |
                            ((unsigned)id[2] << 16) | ((unsigned)id[3] << 24);
            }
        }
    }
    __syncthreads();

    {   // deterministic per-CTA expert-usage partials (4 segs x 32 tokens)
        const int e = tid & 63, seg = tid >> 6;
        float s = 0.0f;
        for (int t = seg * 32; t < seg * 32 + 32; t++)
            s += __expf(sc[t * 65 + e] - mm[t]) * iz[t];
        red[seg * 64 + e] = s;
    }
    __syncthreads();
    if (tid < NEXP)
        g_part[blockIdx.x * NEXP + tid] =
            red[tid] + red[64 + tid] + red[128 + tid] + red[192 + tid];

    // ================= grid-wide barrier =================
    __threadfence();
    __syncthreads();
    if (tid == 0) {
        atomicAdd(&g_done, 1);
        while (atomicAdd(&g_done, 0) < NCTA) __nanosleep(128);
    }
    __syncthreads();
    __threadfence();

    // ================= PHASE B =================
    // aux loss (block 0); NCTA=256 partials
    if (blockIdx.x == 0) {
        const int e = tid & 63, qtr = tid >> 6;
        float s = 0.0f;
        for (int c = qtr * 64; c < qtr * 64 + 64; c++)
            s += g_part[c * NEXP + e];
        sm[tid] = s;
        __syncthreads();
        if (tid < 64) {
            float u = (sm[tid] + sm[64 + tid] + sm[128 + tid] + sm[192 + tid])
                      * (1.0f / (float)NTOK);
            sm[256 + tid] = u * u;
        }
        __syncthreads();
        if (tid < 32) {
            float v = sm[256 + tid] + sm[256 + tid + 32];
            #pragma unroll
            for (int o = 16; o > 0; o >>= 1) v += __shfl_xor_sync(0xffffffffu, v, o);
            if (tid == 0) out[131072] = 64.0f * v;
        }
        __syncthreads();
    }

    // fp64 recompute of top-4 candidates: warps 0-3 -> token base, 4-7 -> base+NCTA
    {
        static __shared__ double sv[8];
        static __shared__ int    se[8];
        const int n = g_cnt1;
        for (int base = blockIdx.x; base < n; base += 2 * NCTA) {
            const int q = base + ((wid >= 4) ? NCTA : 0);
            const bool valid = (q < n);
            int tok = 0, e = 0;
            double s = 0.0;
            if (valid) {
                tok = g_list1[q];
                e = (int)((g_cand[q] >> (8 * (wid & 3))) & 255u);
                const float* xr = x + (size_t)tok * KDIM;
                const float* wr = W + (size_t)e * KDIM;
                double c0 = 0.0, c1 = 0.0, c2 = 0.0, c3 = 0.0;
                #pragma unroll 4
                for (int j = 0; j < 64; j += 4) {
                    c0 += (double)xr[(j + 0) * 32 + lane] * (double)wr[(j + 0) * 32 + lane];
                    c1 += (double)xr[(j + 1) * 32 + lane] * (double)wr[(j + 1) * 32 + lane];
                    c2 += (double)xr[(j + 2) * 32 + lane] * (double)wr[(j + 2) * 32 + lane];
                    c3 += (double)xr[(j + 3) * 32 + lane] * (double)wr[(j + 3) * 32 + lane];
                }
                s = (c0 + c1) + (c2 + c3);
            }
            #pragma unroll
            for (int o = 16; o > 0; o >>= 1) s += __shfl_xor_sync(0xffffffffu, s, o);
            if (lane == 0) { sv[wid] = s; se[wid] = e; }
            __syncthreads();
            if ((tid & 127) == 0) {
                const int g = tid >> 7;                    // 0: base, 1: base+NCTA
                const int qq = base + g * NCTA;
                if (qq < n) {
                    const int tk = g_list1[qq];
                    const double* v = sv + g * 4;
                    const int*    ee = se + g * 4;
                    int b1 = 0;
                    for (int k = 1; k < 4; k++)
                        if (v[k] > v[b1] || (v[k] == v[b1] && ee[k] < ee[b1])) b1 = k;
                    int b2 = (b1 == 0) ? 1 : 0;
                    for (int k = 0; k < 4; k++) {
                        if (k == b1) continue;
                        if (v[k] > v[b2] || (v[k] == v[b2] && ee[k] < ee[b2])) b2 = k;
                    }
                    double e2 = exp(v[b2] - v[b1]);
                    double w1 = 1.0 / (1.0 + e2);
                    out[2 * (size_t)tk]     = (float)ee[b1];
                    out[2 * (size_t)tk + 1] = (float)ee[b2];
                    out[2 * (size_t)NTOK + 2 * (size_t)tk]     = (float)w1;
                    out[2 * (size_t)NTOK + 2 * (size_t)tk + 1] = (float)(e2 * w1);
                }
            }
            __syncthreads();
        }
    }

    // rare full-64 fp64 tokens: warp wi -> experts wi*8..wi*8+7
    {
        static __shared__ double sh[64];
        const int n2 = g_cnt2;
        for (int q = blockIdx.x; q < n2; q += NCTA) {
            const int tok = g_list2[q];
            const float* xr = x + (size_t)tok * KDIM;
            #pragma unroll 1
            for (int e8 = 0; e8 < 8; e8++) {
                const int e = wid * 8 + e8;
                const float* wr = W + (size_t)e * KDIM;
                double c0 = 0.0, c1 = 0.0, c2 = 0.0, c3 = 0.0;
                #pragma unroll 4
                for (int j = 0; j < 64; j += 4) {
                    c0 += (double)xr[(j + 0) * 32 + lane] * (double)wr[(j + 0) * 32 + lane];
                    c1 += (double)xr[(j + 1) * 32 + lane] * (double)wr[(j + 1) * 32 + lane];
                    c2 += (double)xr[(j + 2) * 32 + lane] * (double)wr[(j + 2) * 32 + lane];
                    c3 += (double)xr[(j + 3) * 32 + lane] * (double)wr[(j + 3) * 32 + lane];
                }
                double s = (c0 + c1) + (c2 + c3);
                #pragma unroll
                for (int o = 16; o > 0; o >>= 1) s += __shfl_xor_sync(0xffffffffu, s, o);
                if (lane == 0) sh[e] = s;
            }
            __syncthreads();
            if (tid == 0) {
                double m1 = -1e300, m2 = -1e300; int i1 = 0, i2 = 0;
                for (int e = 0; e < 64; e++)
                    if (sh[e] > m1) { m1 = sh[e]; i1 = e; }
                for (int e = 0; e < 64; e++) {
                    if (e == i1) continue;
                    if (sh[e] > m2) { m2 = sh[e]; i2 = e; }
                }
                double e2 = exp(m2 - m1);
                double w1 = 1.0 / (1.0 + e2);
                out[2 * (size_t)tok]     = (float)i1;
                out[2 * (size_t)tok + 1] = (float)i2;
                out[2 * (size_t)NTOK + 2 * (size_t)tok]     = (float)w1;
                out[2 * (size_t)NTOK + 2 * (size_t)tok + 1] = (float)(e2 * w1);
            }
            __syncthreads();
        }
    }

    // ================= PHASE C: reset for next (graph-replayed) run =========
    __syncthreads();
    if (tid == 0) {
        __threadfence();
        int v = atomicAdd(&g_done2, 1);
        if (v == NCTA - 1) {      // last block out resets all counters
            g_done = 0; g_done2 = 0; g_cnt1 = 0; g_cnt2 = 0;
            __threadfence();
        }
    }
}

extern "C" void kernel_launch(void* const* d_in, const int* in_sizes, int n_in,
                              void* d_out, int out_size) {
    const float* x = (const float*)d_in[0];
    const float* W = (const float*)d_in[1];
    float* out = (float*)d_out;
    cudaFuncSetAttribute(fused_kernel, cudaFuncAttributeMaxDynamicSharedMemorySize, SMEM_REQ);
    fused_kernel<<<NCTA, 256, SMEM_REQ>>>(x, W, out);
}

// round 10
// speedup vs baseline: 1.0623x; 1.0623x over previous
#include <cuda_runtime.h>
#include <cstdint>

// Router_63900523430579 (GB300/sm_103): scores = x[32768,2048] @ W[64,2048]^T
// Fused persistent kernel: tf32 mma.sync GEMM (fragment-packed W, conflict-free
// smem) + top-2 epilogue, grid barrier, fp64 fixup of ambiguous tokens + aux.
// out f32: [0,65536) top2 idx ; [65536,131072) top2 weights ; [131072] aux loss

#define KDIM   2048
#define NTOK   32768
#define NEXP   64
#define MTILE  128
#define NCTA   (NTOK / MTILE)          // 256
#define CK     32
#define NCHUNK (KDIM / CK)             // 64
#define RWX    36                      // x row stride (floats): banks 4*lr+lq, conflict-free
#define XB     (MTILE * RWX * 4)       // 18432 B x per stage
#define WBYTES 8192                    // packed W per chunk
#define STAGEB (XB + WBYTES)           // 26624 B
#define STAGEW (STAGEB / 4)
#define NSTAGE 3
#define SMEM_REQ (NSTAGE * STAGEB)     // 79872 B -> 2 CTA/SM
#define DELTA1 3.0e-3f

__device__ int      g_done, g_done2, g_cnt1, g_cnt2;
__device__ float    g_Wp[NEXP * KDIM];          // fragment-packed W
__device__ float    g_part[NCTA * NEXP];
__device__ int      g_list1[NTOK], g_list2[NTOK];
__device__ unsigned g_cand[NTOK];

__device__ __forceinline__ void mma8(float* d, uint32_t a0, uint32_t a1,
                                     uint32_t a2, uint32_t a3,
                                     uint32_t b0, uint32_t b1) {
    asm volatile("mma.sync.aligned.m16n8k8.row.col.f32.tf32.tf32.f32 "
                 "{%0,%1,%2,%3},{%4,%5,%6,%7},{%8,%9},{%0,%1,%2,%3};"
                 : "+f"(d[0]), "+f"(d[1]), "+f"(d[2]), "+f"(d[3])
                 : "r"(a0), "r"(a1), "r"(a2), "r"(a3), "r"(b0), "r"(b1));
}
__device__ __forceinline__ void cp16(uint32_t s, const void* g) {
    asm volatile("cp.async.cg.shared.global [%0], [%1], 16;\n" :: "r"(s), "l"(g));
}
#define CP_COMMIT() asm volatile("cp.async.commit_group;\n")
#define CP_WAIT(n)  asm volatile("cp.async.wait_group %0;\n" :: "n"(n))

// ---- prep: pack W into per-chunk fragment-contiguous layout + reset ----
// pos(c,s,j,t,p) = c*2048 + (s*8+j)*64 + t*2 + p  holds
//   W[e = j*8 + t/4][k = c*32 + s*8 + (t&3) + 4p]
__global__ void prep_kernel(const float* __restrict__ W) {
    int pi = blockIdx.x * blockDim.x + threadIdx.x;     // 65536 pairs
    if (pi < NEXP * KDIM / 2) {
        int c = pi >> 10, rem = pi & 1023;
        int sj = rem >> 5, t = rem & 31;
        int e = (sj & 7) * 8 + (t >> 2);
        int k = c * 32 + (sj >> 3) * 8 + (t & 3);
        g_Wp[2 * pi]     = W[(size_t)e * KDIM + k];
        g_Wp[2 * pi + 1] = W[(size_t)e * KDIM + k + 4];
    }
    if (pi == 0) { g_done = 0; g_done2 = 0; g_cnt1 = 0; g_cnt2 = 0; }
}

__global__ void __launch_bounds__(256, 2)
fused_kernel(const float* __restrict__ x, const float* __restrict__ W,
             float* __restrict__ out) {
    extern __shared__ float sm[];
    const uint32_t smb = (uint32_t)__cvta_generic_to_shared(sm);
    const int tid = threadIdx.x;
    const int wid = tid >> 5, lane = tid & 31;
    const int lq = lane & 3, lr = lane >> 2;

    // ================= PHASE A: GEMM tile =================
    const float* xg = x + (size_t)blockIdx.x * MTILE * KDIM;

    auto issue_chunk = [&](int c) {
        uint32_t st = smb + (uint32_t)((c % NSTAGE) * STAGEB);
        #pragma unroll
        for (int v = 0; v < 4; v++) {                 // x: 128 rows x 8 f4
            int fi = tid + 256 * v;
            int r = fi >> 3, j = fi & 7;
            cp16(st + (uint32_t)(r * 144 + j * 16),
                 xg + (size_t)r * KDIM + c * CK + j * 4);
        }
        cp16(st + XB + (uint32_t)tid * 16, g_Wp + (size_t)c * 2048 + tid * 4);
        cp16(st + XB + 4096u + (uint32_t)tid * 16,
             g_Wp + (size_t)c * 2048 + 1024 + tid * 4);
        CP_COMMIT();
    };

    float acc[8][4];
    #pragma unroll
    for (int j = 0; j < 8; j++)
        #pragma unroll
        for (int v = 0; v < 4; v++) acc[j][v] = 0.0f;

    issue_chunk(0); issue_chunk(1);

    for (int c = 0; c < NCHUNK; c++) {
        if (c < NCHUNK - 2) CP_WAIT(1);
        else                CP_WAIT(0);
        __syncthreads();
        if (c + 2 < NCHUNK) issue_chunk(c + 2);

        const float* xb = sm + (c % NSTAGE) * STAGEW;
        const float* wb = xb + XB / 4;
        #pragma unroll
        for (int s = 0; s < 4; s++) {
            const float* xr = xb + (wid * 16 + lr) * RWX + s * 8 + lq;
            uint32_t a0 = __float_as_uint(xr[0]);
            uint32_t a1 = __float_as_uint(xr[8 * RWX]);
            uint32_t a2 = __float_as_uint(xr[4]);
            uint32_t a3 = __float_as_uint(xr[8 * RWX + 4]);
            #pragma unroll
            for (int j = 0; j < 8; j++) {
                float2 b = *(const float2*)(wb + (s * 8 + j) * 64 + lane * 2);
                mma8(acc[j], a0, a1, a2, a3,
                     __float_as_uint(b.x), __float_as_uint(b.y));
            }
        }
    }
    __syncthreads();

    // ---- epilogue overlay: sc[128][65], mm[128], iz[128], red[4][64] ----
    float* sc = sm;
    float* mm = sc + 128 * 65;
    float* iz = mm + 128;
    float* red = iz + 128;

    {
        int r0 = wid * 16 + lr;
        #pragma unroll
        for (int j = 0; j < 8; j++) {
            sc[r0 * 65 + j * 8 + 2 * lq]           = acc[j][0];
            sc[r0 * 65 + j * 8 + 2 * lq + 1]       = acc[j][1];
            sc[(r0 + 8) * 65 + j * 8 + 2 * lq]     = acc[j][2];
            sc[(r0 + 8) * 65 + j * 8 + 2 * lq + 1] = acc[j][3];
        }
    }
    __syncthreads();

    if (tid < 128) {    // one token per thread: top-4, softmax, ambiguity routing
        const int t = tid;
        const float* row = sc + t * 65;
        float m[4] = {-3e38f, -3e38f, -3e38f, -3e38f};
        int   id[4] = {0, 0, 0, 0};
        #pragma unroll 8
        for (int e = 0; e < 64; e++) {
            float v = row[e];
            if (v > m[0])      { m[3]=m[2]; id[3]=id[2]; m[2]=m[1]; id[2]=id[1];
                                 m[1]=m[0]; id[1]=id[0]; m[0]=v; id[0]=e; }
            else if (v > m[1]) { m[3]=m[2]; id[3]=id[2]; m[2]=m[1]; id[2]=id[1];
                                 m[1]=v; id[1]=e; }
            else if (v > m[2]) { m[3]=m[2]; id[3]=id[2]; m[2]=v; id[2]=e; }
            else if (v > m[3]) { m[3]=v; id[3]=e; }
        }
        float Z = 0.0f;
        #pragma unroll 8
        for (int e = 0; e < 64; e++) Z += __expf(row[e] - m[0]);
        mm[t] = m[0];
        iz[t] = 1.0f / Z;

        float e2 = __expf(m[1] - m[0]);
        float w1 = 1.0f / (1.0f + e2);
        size_t T = (size_t)blockIdx.x * MTILE + t;
        out[2 * T]     = (float)id[0];
        out[2 * T + 1] = (float)id[1];
        out[2 * (size_t)NTOK + 2 * T]     = w1;
        out[2 * (size_t)NTOK + 2 * T + 1] = e2 * w1;

        if ((m[0] - m[1]) < DELTA1 || (m[1] - m[2]) < DELTA1) {
            if ((m[1] - m[3]) < DELTA1) {
                int q = atomicAdd(&g_cnt2, 1);
                g_list2[q] = (int)T;
            } else {
                int q = atomicAdd(&g_cnt1, 1);
                g_list1[q] = (int)T;
                g_cand[q] = (unsigned)id[0] | ((unsigned)id[1] << 8) |
                            ((unsigned)id[2] << 16) | ((unsigned)id[3] << 24);
            }
        }
    }
    __syncthreads();

    {   // deterministic per-CTA expert-usage partials (4 segs x 32 tokens)
        const int e = tid & 63, seg = tid >> 6;
        float s = 0.0f;
        for (int t = seg * 32; t < seg * 32 + 32; t++)
            s += __expf(sc[t * 65 + e] - mm[t]) * iz[t];
        red[seg * 64 + e] = s;
    }
    __syncthreads();
    if (tid < NEXP)
        g_part[blockIdx.x * NEXP + tid] =
            red[tid] + red[64 + tid] + red[128 + tid] + red[192 + tid];

    // ================= grid-wide barrier =================
    __threadfence();
    __syncthreads();
    if (tid == 0) {
        atomicAdd(&g_done, 1);
        while (atomicAdd(&g_done, 0) < NCTA) __nanosleep(128);
    }
    __syncthreads();
    __threadfence();

    // ================= PHASE B =================
    if (blockIdx.x == 0) {   // aux loss
        const int e = tid & 63, qtr = tid >> 6;
        float s = 0.0f;
        for (int c = qtr * 64; c < qtr * 64 + 64; c++)
            s += g_part[c * NEXP + e];
        sm[tid] = s;
        __syncthreads();
        if (tid < 64) {
            float u = (sm[tid] + sm[64 + tid] + sm[128 + tid] + sm[192 + tid])
                      * (1.0f / (float)NTOK);
            sm[256 + tid] = u * u;
        }
        __syncthreads();
        if (tid < 32) {
            float v = sm[256 + tid] + sm[256 + tid + 32];
            #pragma unroll
            for (int o = 16; o > 0; o >>= 1) v += __shfl_xor_sync(0xffffffffu, v, o);
            if (tid == 0) out[131072] = 64.0f * v;
        }
        __syncthreads();
    }

    // fp64 recompute of top-4 candidates: warps 0-3 -> token base, 4-7 -> base+NCTA
    {
        static __shared__ double sv[8];
        static __shared__ int    se[8];
        const int n = g_cnt1;
        for (int base = blockIdx.x; base < n; base += 2 * NCTA) {
            const int q = base + ((wid >= 4) ? NCTA : 0);
            const bool valid = (q < n);
            int tok = 0, e = 0;
            double s = 0.0;
            if (valid) {
                tok = g_list1[q];
                e = (int)((g_cand[q] >> (8 * (wid & 3))) & 255u);
                const float* xr = x + (size_t)tok * KDIM;
                const float* wr = W + (size_t)e * KDIM;
                double c0 = 0.0, c1 = 0.0, c2 = 0.0, c3 = 0.0;
                #pragma unroll 4
                for (int j = 0; j < 64; j += 4) {
                    c0 += (double)xr[(j + 0) * 32 + lane] * (double)wr[(j + 0) * 32 + lane];
                    c1 += (double)xr[(j + 1) * 32 + lane] * (double)wr[(j + 1) * 32 + lane];
                    c2 += (double)xr[(j + 2) * 32 + lane] * (double)wr[(j + 2) * 32 + lane];
                    c3 += (double)xr[(j + 3) * 32 + lane] * (double)wr[(j + 3) * 32 + lane];
                }
                s = (c0 + c1) + (c2 + c3);
            }
            #pragma unroll
            for (int o = 16; o > 0; o >>= 1) s += __shfl_xor_sync(0xffffffffu, s, o);
            if (lane == 0) { sv[wid] = s; se[wid] = e; }
            __syncthreads();
            if ((tid & 127) == 0) {
                const int g = tid >> 7;
                const int qq = base + g * NCTA;
                if (qq < n) {
                    const int tk = g_list1[qq];
                    const double* v = sv + g * 4;
                    const int*    ee = se + g * 4;
                    int b1 = 0;
                    for (int k = 1; k < 4; k++)
                        if (v[k] > v[b1] || (v[k] == v[b1] && ee[k] < ee[b1])) b1 = k;
                    int b2 = (b1 == 0) ? 1 : 0;
                    for (int k = 0; k < 4; k++) {
                        if (k == b1) continue;
                        if (v[k] > v[b2] || (v[k] == v[b2] && ee[k] < ee[b2])) b2 = k;
                    }
                    double e2 = exp(v[b2] - v[b1]);
                    double w1 = 1.0 / (1.0 + e2);
                    out[2 * (size_t)tk]     = (float)ee[b1];
                    out[2 * (size_t)tk + 1] = (float)ee[b2];
                    out[2 * (size_t)NTOK + 2 * (size_t)tk]     = (float)w1;
                    out[2 * (size_t)NTOK + 2 * (size_t)tk + 1] = (float)(e2 * w1);
                }
            }
            __syncthreads();
        }
    }

    // rare full-64 fp64 tokens
    {
        static __shared__ double sh[64];
        const int n2 = g_cnt2;
        for (int q = blockIdx.x; q < n2; q += NCTA) {
            const int tok = g_list2[q];
            const float* xr = x + (size_t)tok * KDIM;
            #pragma unroll 1
            for (int e8 = 0; e8 < 8; e8++) {
                const int e = wid * 8 + e8;
                const float* wr = W + (size_t)e * KDIM;
                double c0 = 0.0, c1 = 0.0, c2 = 0.0, c3 = 0.0;
                #pragma unroll 4
                for (int j = 0; j < 64; j += 4) {
                    c0 += (double)xr[(j + 0) * 32 + lane] * (double)wr[(j + 0) * 32 + lane];
                    c1 += (double)xr[(j + 1) * 32 + lane] * (double)wr[(j + 1) * 32 + lane];
                    c2 += (double)xr[(j + 2) * 32 + lane] * (double)wr[(j + 2) * 32 + lane];
                    c3 += (double)xr[(j + 3) * 32 + lane] * (double)wr[(j + 3) * 32 + lane];
                }
                double s = (c0 + c1) + (c2 + c3);
                #pragma unroll
                for (int o = 16; o > 0; o >>= 1) s += __shfl_xor_sync(0xffffffffu, s, o);
                if (lane == 0) sh[e] = s;
            }
            __syncthreads();
            if (tid == 0) {
                double m1 = -1e300, m2 = -1e300; int i1 = 0, i2 = 0;
                for (int e = 0; e < 64; e++)
                    if (sh[e] > m1) { m1 = sh[e]; i1 = e; }
                for (int e = 0; e < 64; e++) {
                    if (e == i1) continue;
                    if (sh[e] > m2) { m2 = sh[e]; i2 = e; }
                }
                double e2 = exp(m2 - m1);
                double w1 = 1.0 / (1.0 + e2);
                out[2 * (size_t)tok]     = (float)i1;
                out[2 * (size_t)tok + 1] = (float)i2;
                out[2 * (size_t)NTOK + 2 * (size_t)tok]     = (float)w1;
                out[2 * (size_t)NTOK + 2 * (size_t)tok + 1] = (float)(e2 * w1);
            }
            __syncthreads();
        }
    }

    // ================= PHASE C: reset for next graph replay =================
    __syncthreads();
    if (tid == 0) {
        __threadfence();
        int v = atomicAdd(&g_done2, 1);
        if (v == NCTA - 1) {
            g_done = 0; g_done2 = 0; g_cnt1 = 0; g_cnt2 = 0;
            __threadfence();
        }
    }
}

extern "C" void kernel_launch(void* const* d_in, const int* in_sizes, int n_in,
                              void* d_out, int out_size) {
    const float* x = (const float*)d_in[0];
    const float* W = (const float*)d_in[1];
    float* out = (float*)d_out;
    cudaFuncSetAttribute(fused_kernel, cudaFuncAttributeMaxDynamicSharedMemorySize, SMEM_REQ);
    prep_kernel<<<256, 256>>>(W);
    fused_kernel<<<NCTA, 256, SMEM_REQ>>>(x, W, out);
}